// round 6
// baseline (speedup 1.0000x reference)
#include <cuda_runtime.h>
#include <math.h>

#define NUM_BODY 30
#define NPRED    32
#define NFORM    2
#define KTOP     3
#define SIGMA    0.1f
#define TEMP     0.07f
#define TOL      0.02f
#define DS_PITCH 31   // coprime with 32 banks -> conflict-free row reads

__device__ __forceinline__ float case_rrf(float xa, float x3) {
    float ea = __expf(xa * (1.0f / TEMP));
    float e3 = __expf(x3 * (1.0f / TEMP));
    return __fdividef(fmaf(ea, xa, e3 * x3), ea + 2.0f + e3);
}

__global__ __launch_bounds__(32)
void logic_model_kernel(const float* __restrict__ t,        // (B,1)
                        const float* __restrict__ ds,       // (B,30)
                        const float* __restrict__ pi,       // (3,)
                        const float* __restrict__ A,        // (2,32)
                        const float* __restrict__ base_p,   // (1,)
                        const float* __restrict__ fw,       // (2,)
                        const float* __restrict__ prob,     // (4,)
                        float* __restrict__ out,            // (B,3)
                        int n)
{
    __shared__ float sDS[32 * DS_PITCH];

    const int lane    = threadIdx.x;
    const int f       = blockIdx.x & 1;
    const int rowBase = (blockIdx.x >> 1) * 32;
    const int b       = rowBase + lane;
    const int bc      = min(b, n - 1);
    const bool act    = (b < n);

    // ---- coalesced staged load of the 32x30 ds tile ----
    // rows*30 floats are contiguous; load as float2 (always row-pair aligned
    // since 30 is even), 2 lines per LDG.64 instead of 30.
    {
        const int rows = min(32, n - rowBase);
        const int half = rows * (NUM_BODY / 2);           // # of float2
        const float2* g2 = (const float2*)(ds + rowBase * NUM_BODY);
        for (int e2 = lane; e2 < half; e2 += 32) {
            float2 v = g2[e2];
            int e = 2 * e2;
            int r = e / NUM_BODY;
            int c = e - r * NUM_BODY;
            sDS[r * DS_PITCH + c]     = v.x;
            sDS[r * DS_PITCH + c + 1] = v.y;
        }
    }

    // ---- other loads (issue while smem stores drain) ----
    const float tb = t[bc];
    float av[NPRED];
    {
        const float4* A4 = (const float4*)(A + f * NPRED);
        #pragma unroll
        for (int q = 0; q < NPRED / 4; ++q) {
            float4 v = A4[q];
            av[4 * q]     = v.x;
            av[4 * q + 1] = v.y;
            av[4 * q + 2] = v.z;
            av[4 * q + 3] = v.w;
        }
    }
    const float base = base_p[0];
    const float p0 = prob[0], p1 = prob[1], p2 = prob[2], p3 = prob[3];
    const float fwf  = fw[f];
    const float lpi0 = __logf(pi[0]);
    const float lpif = __logf(pi[1 + f]);

    // ---- 4-case rrf / weight table ----
    float rrfT[4], wT[4];
    rrfT[0] = case_rrf(p0, (1.0f - p0) * p3);
    rrfT[1] = case_rrf(p1, (1.0f - p1) * p3);
    rrfT[2] = case_rrf(p2, (1.0f - p2) * p3);
    rrfT[3] = case_rrf(0.0f, p3);
    #pragma unroll
    for (int cs = 0; cs < 4; ++cs) wT[cs] = __expf(-rrfT[cs] * (1.0f / TEMP));

    // ---- top-3 via rank-by-comparison + single ballot ----
    int s0, s1, s2;
    {
        const float mine = av[lane];
        int rank = 0;
        #pragma unroll
        for (int k = 0; k < NPRED; ++k) {
            float vk = av[k];
            rank += (vk > mine || (vk == mine && k < lane)) ? 1 : 0;
        }
        unsigned m = __ballot_sync(0xffffffffu, rank < KTOP);
        s0 = __ffs(m) - 1;  m &= m - 1;
        s1 = __ffs(m) - 1;  m &= m - 1;
        s2 = __ffs(m) - 1;
    }
    const int sel[KTOP] = {s0, s1, s2};
    float pv3[3]; int pc3[3], qc3[3];
    {
        const int pa[3] = {0, 0, 1};
        const int pb[3] = {1, 2, 2};
        #pragma unroll
        for (int p = 0; p < 3; ++p) {
            bool vd = (sel[pa[p]] < NUM_BODY) && (sel[pb[p]] < NUM_BODY);
            pv3[p] = vd ? 1.0f : 0.0f;
            pc3[p] = min(sel[pa[p]], NUM_BODY - 1);
            qc3[p] = min(sel[pb[p]], NUM_BODY - 1);
        }
    }

    if (f == 0 && act) out[b * 3 + 0] = __logf(base) - tb * base + lpi0;

    __syncwarp();
    const float* myds = &sDS[lane * DS_PITCH];

    // ---- formula body: 4-way partial dot + fmax tree ----
    float dsl[NUM_BODY];
    #pragma unroll
    for (int j = 0; j < NUM_BODY; ++j) dsl[j] = myds[j];

    float dotP[4] = {av[NUM_BODY], av[NUM_BODY + 1], 0.0f, 0.0f};
    float mbtP[4] = {0.0f, 0.0f, 0.0f, 0.0f};
    #pragma unroll
    for (int j = 0; j < NUM_BODY; ++j) {
        float dv  = dsl[j];
        float aij = av[j];
        int q = j & 3;
        if (dv <= tb) {
            dotP[q] += aij;
            mbtP[q] = fmaxf(mbtP[q], dv * aij);
        }
    }
    float dot = (dotP[0] + dotP[1]) + (dotP[2] + dotP[3]);
    float mbt = fmaxf(fmaxf(mbtP[0], mbtP[1]), fmaxf(mbtP[2], mbtP[3]));

    float feat = __expf(-fabsf(dot - (float)KTOP) * (1.0f / SIGMA));

    float wsum = 0.0f, wxsum = 0.0f, pvsum = 0.0f;
    #pragma unroll
    for (int p = 0; p < 3; ++p) {
        float td = myds[pc3[p]] - myds[qc3[p]];   // dynamic LDS, conflict-free-ish
        int cs = 3;
        if (td > TOL) cs = 0;
        else if (fabsf(td) < TOL) cs = 1;
        else if (td < -TOL) cs = 2;
        float pv = pv3[p];
        float w  = pv * wT[cs];
        wsum  += w;
        wxsum += w * rrfT[cs];
        pvsum += pv;
    }
    float col = __fdividef(wxsum, fmaxf(wsum, 1e-30f));
    if (!(pvsum > 0.0f)) col = 1.0f;
    feat *= col;

    float sg  = __fdividef(1.0f, 1.0f + __expf(-(tb - mbt)));
    float cur = fmaf(sg * feat, fwf, base);
    float lps = __logf(cur) + (-tb * cur + sg * (-mbt * base + mbt * cur)) + lpif;
    if (act) out[b * 3 + 1 + f] = lps;
}

extern "C" void kernel_launch(void* const* d_in, const int* in_sizes, int n_in,
                              void* d_out, int out_size)
{
    const float* t    = (const float*)d_in[0];
    const float* ds   = (const float*)d_in[1];
    const float* pi   = (const float*)d_in[2];
    const float* A    = (const float*)d_in[3];
    const float* base = (const float*)d_in[4];
    const float* fw   = (const float*)d_in[5];
    const float* prob = (const float*)d_in[6];
    float* out = (float*)d_out;

    const int n = in_sizes[0];
    const int rowblks = (n + 31) / 32;
    const int blocks  = rowblks * NFORM;
    logic_model_kernel<<<blocks, 32>>>(t, ds, pi, A, base, fw, prob, out, n);
}